// round 9
// baseline (speedup 1.0000x reference)
#include <cuda_runtime.h>

#define NN 100000
#define NE 1200000
#define NB1 98   // ceil(NN/1024) scan blocks

// Scratch (device globals — no allocation allowed).
__device__ int    g_is64;           // 1 if edge_index arrives as int64
__device__ int    g_deg[NN];        // in-degree
__device__ int    g_cur[NN];        // scan -> segment start; after fill -> segment end
__device__ int    g_bsum[128];      // scan block sums
__device__ int    g_esrc[NE];       // CSR: source node per edge slot (grouped by dst)
__device__ float4 g_h[NN * 16];     // relu(layer1)  [NN,64]
__device__ float4 g_hl[NN * 8];     // h @ W2_l      [NN,32]

// Edge fetch helpers: harness may deliver edge_index as int32 (downcast) or
// raw int64. Values < 2^31 in either case; int64 little-endian low word is
// at even int32 slot.
__device__ __forceinline__ int edge_src(const int* __restrict__ ei, int e) {
    return g_is64 ? __ldg(&ei[2 * e]) : __ldg(&ei[e]);
}
__device__ __forceinline__ int edge_dst(const int* __restrict__ ei, int e) {
    return g_is64 ? __ldg(&ei[2 * NE + 2 * e]) : __ldg(&ei[NE + e]);
}

// ---------------------------------------------------------------------------
// K-1: dtype sniffer. If int64 (all ids < 100000 => high words 0), odd int32
// slots 1,3,5,7 are all zero. If int32, they are random node ids (P[all 0]
// ~ 1e-20).
// ---------------------------------------------------------------------------
__global__ void k_sniff(const int* __restrict__ ei) {
    if (threadIdx.x == 0 && blockIdx.x == 0) {
        int o = ei[1] | ei[3] | ei[5] | ei[7];
        g_is64 = (o == 0) ? 1 : 0;
    }
}

// ---------------------------------------------------------------------------
// K0: zero degree histogram
// ---------------------------------------------------------------------------
__global__ void k_zero() {
    int t = blockIdx.x * blockDim.x + threadIdx.x;
    if (t < NN) g_deg[t] = 0;
}

// ---------------------------------------------------------------------------
// K1: degree histogram (int atomics only; index-guarded)
// ---------------------------------------------------------------------------
__global__ void k_deg(const int* __restrict__ ei) {
    int e = blockIdx.x * blockDim.x + threadIdx.x;
    if (e >= NE) return;
    unsigned dst = (unsigned)edge_dst(ei, e);
    if (dst < NN) atomicAdd(&g_deg[dst], 1);
}

// ---------------------------------------------------------------------------
// K2: per-block exclusive scan of g_deg (1024 elems/block, 256 thr x 4)
// ---------------------------------------------------------------------------
__global__ void __launch_bounds__(256) k_scan1() {
    __shared__ int s[256];
    int b = blockIdx.x, t = threadIdx.x;
    int base = b * 1024 + t * 4;
    int v0 = (base + 0 < NN) ? g_deg[base + 0] : 0;
    int v1 = (base + 1 < NN) ? g_deg[base + 1] : 0;
    int v2 = (base + 2 < NN) ? g_deg[base + 2] : 0;
    int v3 = (base + 3 < NN) ? g_deg[base + 3] : 0;
    int tsum = v0 + v1 + v2 + v3;
    s[t] = tsum;
    __syncthreads();
    for (int off = 1; off < 256; off <<= 1) {
        int x = (t >= off) ? s[t - off] : 0;
        __syncthreads();
        if (t >= off) s[t] += x;
        __syncthreads();
    }
    int excl = s[t] - tsum;
    if (t == 255) g_bsum[b] = s[t];
    int p = excl;
    if (base + 0 < NN) g_cur[base + 0] = p;
    p += v0;
    if (base + 1 < NN) g_cur[base + 1] = p;
    p += v1;
    if (base + 2 < NN) g_cur[base + 2] = p;
    p += v2;
    if (base + 3 < NN) g_cur[base + 3] = p;
}

// K2b: exclusive scan of the 98 block sums (trivial serial)
__global__ void k_scan2() {
    if (threadIdx.x == 0 && blockIdx.x == 0) {
        int acc = 0;
        for (int i = 0; i < NB1; i++) { int v = g_bsum[i]; g_bsum[i] = acc; acc += v; }
    }
}

// K2c: add block offsets -> g_cur[i] = global segment start
__global__ void k_scan3() {
    int i = blockIdx.x * blockDim.x + threadIdx.x;
    if (i < NN) g_cur[i] += g_bsum[i >> 10];
}

// ---------------------------------------------------------------------------
// K3: fill CSR edge array. After this, g_cur[n] == segment END for node n.
// ---------------------------------------------------------------------------
__global__ void k_fill(const int* __restrict__ ei) {
    int e = blockIdx.x * blockDim.x + threadIdx.x;
    if (e >= NE) return;
    unsigned src = (unsigned)edge_src(ei, e);
    unsigned dst = (unsigned)edge_dst(ei, e);
    if (src >= NN || dst >= NN) return;
    int pos = atomicAdd(&g_cur[dst], 1);
    if ((unsigned)pos < NE) g_esrc[pos] = (int)src;
}

// ---------------------------------------------------------------------------
// K4: fused layer 1.
// Phase A (gather): 512 thr = 32 nodes x 16 chan-chunks; mean-agg neighbors.
// Phase B (dense):  h = relu(agg @ W1_l + x @ W1_r + b1)
// ---------------------------------------------------------------------------
__global__ void __launch_bounds__(512) k_layer1(const float4* __restrict__ x4,
                                                const float4* __restrict__ Wl,
                                                const float4* __restrict__ Wr,
                                                const float4* __restrict__ b1) {
    __shared__ float4 sWl[1024];
    __shared__ float4 sWr[1024];
    __shared__ float4 sAgg[32 * 16];
    __shared__ float4 sB[16];
    int tid = threadIdx.x;
    for (int i = tid; i < 1024; i += 512) { sWl[i] = Wl[i]; sWr[i] = Wr[i]; }
    if (tid < 16) sB[tid] = b1[tid];

    int slot = tid >> 4;           // 0..31
    int c    = tid & 15;           // channel chunk
    int n    = blockIdx.x * 32 + slot;

    float4 acc = make_float4(0.f, 0.f, 0.f, 0.f);
    if (n < NN) {
        int end = g_cur[n];
        int d   = g_deg[n];
        for (int j = end - d; j < end; j++) {
            int s = g_esrc[j];   // same addr across 16 lanes -> broadcast
            float4 v = __ldg(&x4[s * 16 + c]);
            acc.x += v.x; acc.y += v.y; acc.z += v.z; acc.w += v.w;
        }
        float inv = 1.0f / fmaxf((float)d, 1.0f);
        acc.x *= inv; acc.y *= inv; acc.z *= inv; acc.w *= inv;
    }
    sAgg[slot * 16 + c] = acc;
    __syncthreads();

    int j4 = c;
    if (n >= NN) return;
    float4 accl = make_float4(0.f, 0.f, 0.f, 0.f);
    float4 accr = make_float4(0.f, 0.f, 0.f, 0.f);
#pragma unroll 4
    for (int k4 = 0; k4 < 16; k4++) {
        float4 a  = sAgg[slot * 16 + k4];
        float4 xv = __ldg(&x4[n * 16 + k4]);
        float4 wl0 = sWl[(k4 * 4 + 0) * 16 + j4];
        float4 wl1 = sWl[(k4 * 4 + 1) * 16 + j4];
        float4 wl2 = sWl[(k4 * 4 + 2) * 16 + j4];
        float4 wl3 = sWl[(k4 * 4 + 3) * 16 + j4];
        float4 wr0 = sWr[(k4 * 4 + 0) * 16 + j4];
        float4 wr1 = sWr[(k4 * 4 + 1) * 16 + j4];
        float4 wr2 = sWr[(k4 * 4 + 2) * 16 + j4];
        float4 wr3 = sWr[(k4 * 4 + 3) * 16 + j4];
        accl.x += a.x * wl0.x + a.y * wl1.x + a.z * wl2.x + a.w * wl3.x;
        accl.y += a.x * wl0.y + a.y * wl1.y + a.z * wl2.y + a.w * wl3.y;
        accl.z += a.x * wl0.z + a.y * wl1.z + a.z * wl2.z + a.w * wl3.z;
        accl.w += a.x * wl0.w + a.y * wl1.w + a.z * wl2.w + a.w * wl3.w;
        accr.x += xv.x * wr0.x + xv.y * wr1.x + xv.z * wr2.x + xv.w * wr3.x;
        accr.y += xv.x * wr0.y + xv.y * wr1.y + xv.z * wr2.y + xv.w * wr3.y;
        accr.z += xv.x * wr0.z + xv.y * wr1.z + xv.z * wr2.z + xv.w * wr3.z;
        accr.w += xv.x * wr0.w + xv.y * wr1.w + xv.z * wr2.w + xv.w * wr3.w;
    }
    float4 bb = sB[j4];
    float4 r;
    r.x = fmaxf(accl.x + accr.x + bb.x, 0.f);
    r.y = fmaxf(accl.y + accr.y + bb.y, 0.f);
    r.z = fmaxf(accl.z + accr.z + bb.z, 0.f);
    r.w = fmaxf(accl.w + accr.w + bb.w, 0.f);
    g_h[n * 16 + j4] = r;
}

// ---------------------------------------------------------------------------
// K5: hl = h @ W2_l  [NN,32]  (pre-multiply: agg is linear, halves gather)
// ---------------------------------------------------------------------------
__global__ void __launch_bounds__(256) k_hl(const float4* __restrict__ W2l) {
    __shared__ float4 sW[512];
    int tid = threadIdx.x;
    for (int i = tid; i < 512; i += 256) sW[i] = W2l[i];
    __syncthreads();

    int j4   = tid & 7;
    int slot = tid >> 3;
    int base = blockIdx.x * 128 + slot;

    float4 acc[4];
    int nidx[4]; bool ok[4];
#pragma unroll
    for (int u = 0; u < 4; u++) {
        int n = base + 32 * u;
        ok[u] = (n < NN);
        nidx[u] = ok[u] ? n : (NN - 1);
        acc[u] = make_float4(0.f, 0.f, 0.f, 0.f);
    }
#pragma unroll 4
    for (int k4 = 0; k4 < 16; k4++) {
        float4 w0 = sW[(k4 * 4 + 0) * 8 + j4];
        float4 w1 = sW[(k4 * 4 + 1) * 8 + j4];
        float4 w2 = sW[(k4 * 4 + 2) * 8 + j4];
        float4 w3 = sW[(k4 * 4 + 3) * 8 + j4];
#pragma unroll
        for (int u = 0; u < 4; u++) {
            float4 h = g_h[nidx[u] * 16 + k4];
            acc[u].x += h.x * w0.x + h.y * w1.x + h.z * w2.x + h.w * w3.x;
            acc[u].y += h.x * w0.y + h.y * w1.y + h.z * w2.y + h.w * w3.y;
            acc[u].z += h.x * w0.z + h.y * w1.z + h.z * w2.z + h.w * w3.z;
            acc[u].w += h.x * w0.w + h.y * w1.w + h.z * w2.w + h.w * w3.w;
        }
    }
#pragma unroll
    for (int u = 0; u < 4; u++)
        if (ok[u]) g_hl[nidx[u] * 8 + j4] = acc[u];
}

// ---------------------------------------------------------------------------
// K6: fused layer 2: out = mean-agg(hl) + h @ W2_r + b2
// ---------------------------------------------------------------------------
__global__ void __launch_bounds__(512) k_layer2(const float4* __restrict__ W2r,
                                                const float4* __restrict__ b2,
                                                float4* __restrict__ out4) {
    __shared__ float4 sW[512];
    __shared__ float4 sAgg[64 * 8];
    __shared__ float4 sB[8];
    int tid = threadIdx.x;
    if (tid < 512) sW[tid] = W2r[tid];
    if (tid < 8) sB[tid] = b2[tid];

    int slot = tid >> 3;          // 0..63
    int c    = tid & 7;
    int n    = blockIdx.x * 64 + slot;

    float4 acc = make_float4(0.f, 0.f, 0.f, 0.f);
    if (n < NN) {
        int end = g_cur[n];
        int d   = g_deg[n];
        for (int j = end - d; j < end; j++) {
            int s = g_esrc[j];
            float4 v = __ldg(&g_hl[s * 8 + c]);
            acc.x += v.x; acc.y += v.y; acc.z += v.z; acc.w += v.w;
        }
        float inv = 1.0f / fmaxf((float)d, 1.0f);
        acc.x *= inv; acc.y *= inv; acc.z *= inv; acc.w *= inv;
    }
    sAgg[slot * 8 + c] = acc;
    __syncthreads();

    int j4 = c;
    if (n >= NN) return;
    float4 a2 = make_float4(0.f, 0.f, 0.f, 0.f);
#pragma unroll 4
    for (int k4 = 0; k4 < 16; k4++) {
        float4 h  = g_h[n * 16 + k4];
        float4 w0 = sW[(k4 * 4 + 0) * 8 + j4];
        float4 w1 = sW[(k4 * 4 + 1) * 8 + j4];
        float4 w2 = sW[(k4 * 4 + 2) * 8 + j4];
        float4 w3 = sW[(k4 * 4 + 3) * 8 + j4];
        a2.x += h.x * w0.x + h.y * w1.x + h.z * w2.x + h.w * w3.x;
        a2.y += h.x * w0.y + h.y * w1.y + h.z * w2.y + h.w * w3.y;
        a2.z += h.x * w0.z + h.y * w1.z + h.z * w2.z + h.w * w3.z;
        a2.w += h.x * w0.w + h.y * w1.w + h.z * w2.w + h.w * w3.w;
    }
    float4 ag = sAgg[slot * 8 + j4];
    float4 bb = sB[j4];
    float4 r;
    r.x = a2.x + ag.x + bb.x;
    r.y = a2.y + ag.y + bb.y;
    r.z = a2.z + ag.z + bb.z;
    r.w = a2.w + ag.w + bb.w;
    out4[n * 8 + j4] = r;
}

// ---------------------------------------------------------------------------
// Launch. Inputs identified BY SIZE (robust to metadata ordering):
//   x: 6,400,000   edge_index: 2,400,000   W1_l/W1_r: 4,096 (l first)
//   b1: 64         W2_l/W2_r: 2,048 (l first)   b2: 32
// output: [100000,32] f32
// ---------------------------------------------------------------------------
extern "C" void kernel_launch(void* const* d_in, const int* in_sizes, int n_in,
                              void* d_out, int out_size) {
    const float4* x4  = 0;
    const int*    ei  = 0;
    const float4* W1l = 0, *W1r = 0, *b1 = 0;
    const float4* W2l = 0, *W2r = 0, *b2 = 0;

    for (int i = 0; i < n_in; i++) {
        switch (in_sizes[i]) {
            case 6400000: x4 = (const float4*)d_in[i]; break;
            case 2400000: ei = (const int*)d_in[i]; break;
            case 4096:    if (!W1l) W1l = (const float4*)d_in[i];
                          else      W1r = (const float4*)d_in[i]; break;
            case 64:      b1 = (const float4*)d_in[i]; break;
            case 2048:    if (!W2l) W2l = (const float4*)d_in[i];
                          else      W2r = (const float4*)d_in[i]; break;
            case 32:      b2 = (const float4*)d_in[i]; break;
            default: break;
        }
    }
    if (!x4 || !ei || !W1l || !W1r || !b1 || !W2l || !W2r || !b2) return;

    float4* out4 = (float4*)d_out;

    k_sniff<<<1, 32>>>(ei);
    k_zero<<<(NN + 255) / 256, 256>>>();
    k_deg<<<(NE + 255) / 256, 256>>>(ei);
    k_scan1<<<NB1, 256>>>();
    k_scan2<<<1, 32>>>();
    k_scan3<<<(NN + 255) / 256, 256>>>();
    k_fill<<<(NE + 255) / 256, 256>>>(ei);
    k_layer1<<<(NN + 31) / 32, 512>>>(x4, W1l, W1r, b1);
    k_hl<<<(NN + 127) / 128, 256>>>(W2l);
    k_layer2<<<(NN + 63) / 64, 512>>>(W2r, b2, out4);
}